// round 4
// baseline (speedup 1.0000x reference)
#include <cuda_runtime.h>
#include <cuda_bf16.h>
#include <math.h>

// Problem constants
#define NROWS  65536      // 64*32*32
#define DDIM   256
#define KCODES 1024
#define QELEMS (65536L*256L)

// GEMM tiling
#define BM 128
#define BN 128
#define BKC 16
#define SPAD 4            // smem row padding (floats)

__device__ float g_enorm[KCODES];
__device__ float g_xnorm[NROWS];
__device__ int   g_hist[KCODES];
__device__ int   g_idx[NROWS];

// ---------------------------------------------------------------------------
// Kernel 0: X[row] = sequential fp32 sum of fl(x*x), ascending order —
// replicates XLA:CPU's scalar sequential row reduction bitwise.
// One thread per row. Loads vectorized, arithmetic strictly sequential.
// ---------------------------------------------------------------------------
__global__ void vq_xnorm_kernel(const float* __restrict__ A) {
    int row = blockIdx.x * 256 + threadIdx.x;
    const float4* p = (const float4*)(A + (long)row * DDIM);
    float s = 0.0f;
    #pragma unroll 8
    for (int j = 0; j < DDIM / 4; ++j) {
        float4 v = p[j];
        s = __fadd_rn(s, __fmul_rn(v.x, v.x));
        s = __fadd_rn(s, __fmul_rn(v.y, v.y));
        s = __fadd_rn(s, __fmul_rn(v.z, v.z));
        s = __fadd_rn(s, __fmul_rn(v.w, v.w));
    }
    g_xnorm[row] = s;
}

// ---------------------------------------------------------------------------
// Kernel 1: codebook row norms (sequential fp32, same discipline) + zero hist.
// One thread per code.
// ---------------------------------------------------------------------------
__global__ void vq_prep_kernel(const float* __restrict__ cb) {
    int w = blockIdx.x * 256 + threadIdx.x;    // 4 blocks x 256 = 1024
    if (w < KCODES) g_hist[w] = 0;
    const float4* p = (const float4*)(cb + (long)w * DDIM);
    float s = 0.0f;
    #pragma unroll 8
    for (int j = 0; j < DDIM / 4; ++j) {
        float4 v = p[j];
        s = __fadd_rn(s, __fmul_rn(v.x, v.x));
        s = __fadd_rn(s, __fmul_rn(v.y, v.y));
        s = __fadd_rn(s, __fmul_rn(v.z, v.z));
        s = __fadd_rn(s, __fmul_rn(v.w, v.w));
    }
    g_enorm[w] = s;
}

// ---------------------------------------------------------------------------
// Kernel 2: fused fp32 GEMM + argmin.
// dot accumulated as a single ascending-K fp32 fma chain (matches any sane
// fp32 reference GEMM to ~1e-8 << ulp(256)).
// Distance replicates the reference EXPRESSION bitwise:
//   d = fl( fl(X + E) - fl(2*dot) )   [2*dot exact; explicit rn intrinsics,
//   no fma contraction]  -> reproduces the catastrophic-absorption rounding
//   that decides the near-tie rows.
// ---------------------------------------------------------------------------
__global__ void __launch_bounds__(256, 2)
vq_argmin_kernel(const float* __restrict__ A,     // f_emb flat [N, D]
                 const float* __restrict__ B,     // codebook   [K, D]
                 float* __restrict__ out,         // d_out (float)
                 long out_size) {
    __shared__ float As[BKC][BM + SPAD];
    __shared__ float Bs[BKC][BN + SPAD];

    const int tid = threadIdx.x;
    const int tx  = tid & 15;        // 0..15  column group
    const int ty  = tid >> 4;        // 0..15  row group
    const int row0 = blockIdx.x * BM;

    float runmin[8];
    int   runidx[8];
    float xv[8];
    #pragma unroll
    for (int i = 0; i < 8; ++i) {
        runmin[i] = INFINITY; runidx[i] = 0x7fffffff;
        int rl = (i < 4) ? (ty * 4 + i) : (64 + ty * 4 + (i - 4));
        xv[i] = g_xnorm[row0 + rl];
    }

    for (int nt = 0; nt < KCODES / BN; ++nt) {
        const int col0 = nt * BN;
        float acc[8][8];
        #pragma unroll
        for (int i = 0; i < 8; ++i)
            #pragma unroll
            for (int j = 0; j < 8; ++j) acc[i][j] = 0.f;

        for (int kt = 0; kt < DDIM; kt += BKC) {
            __syncthreads();
            #pragma unroll
            for (int l = 0; l < 2; ++l) {
                int f  = tid + l * 256;      // 0..511
                int r  = f >> 2;             // row within tile (0..127)
                int dc = (f & 3) * 4;        // d sub-offset (0,4,8,12)
                float4 va = *(const float4*)(A + (long)(row0 + r) * DDIM + kt + dc);
                As[dc + 0][r] = va.x; As[dc + 1][r] = va.y;
                As[dc + 2][r] = va.z; As[dc + 3][r] = va.w;
                float4 vb = *(const float4*)(B + (long)(col0 + r) * DDIM + kt + dc);
                Bs[dc + 0][r] = vb.x; Bs[dc + 1][r] = vb.y;
                Bs[dc + 2][r] = vb.z; Bs[dc + 3][r] = vb.w;
            }
            __syncthreads();

            #pragma unroll
            for (int dd = 0; dd < BKC; ++dd) {
                float a[8], b[8];
                float4 t0 = *(const float4*)&As[dd][ty * 4];
                float4 t1 = *(const float4*)&As[dd][64 + ty * 4];
                a[0]=t0.x; a[1]=t0.y; a[2]=t0.z; a[3]=t0.w;
                a[4]=t1.x; a[5]=t1.y; a[6]=t1.z; a[7]=t1.w;
                float4 u0 = *(const float4*)&Bs[dd][tx * 4];
                float4 u1 = *(const float4*)&Bs[dd][64 + tx * 4];
                b[0]=u0.x; b[1]=u0.y; b[2]=u0.z; b[3]=u0.w;
                b[4]=u1.x; b[5]=u1.y; b[6]=u1.z; b[7]=u1.w;
                #pragma unroll
                for (int i = 0; i < 8; ++i)
                    #pragma unroll
                    for (int j = 0; j < 8; ++j)
                        acc[i][j] = fmaf(a[i], b[j], acc[i][j]);
            }
        }

        // Epilogue: d = fl(fl(X+E) - 2*dot), running first-min (lowest index).
        #pragma unroll
        for (int cj = 0; cj < 8; ++cj) {
            int col = col0 + ((cj < 4) ? (tx * 4 + cj) : (64 + tx * 4 + (cj - 4)));
            float en = g_enorm[col];
            #pragma unroll
            for (int ri = 0; ri < 8; ++ri) {
                float t  = __fadd_rn(xv[ri], en);
                float sc = __fsub_rn(t, __fmul_rn(2.0f, acc[ri][cj]));
                if (sc < runmin[ri]) { runmin[ri] = sc; runidx[ri] = col; }
            }
        }
    }

    // Cross-thread reduction: 16 column-threads per row, lowest index on tie.
    __syncthreads();
    float* rmin = &As[0][0];          // 2048 floats needed, 2112 available
    int*   ridx = (int*)&Bs[0][0];
    #pragma unroll
    for (int ri = 0; ri < 8; ++ri) {
        int rl = (ri < 4) ? (ty * 4 + ri) : (64 + ty * 4 + (ri - 4));
        rmin[rl * 16 + tx] = runmin[ri];
        ridx[rl * 16 + tx] = runidx[ri];
    }
    __syncthreads();
    if (tid < BM) {
        float best = INFINITY; int bi = 0x7fffffff;
        #pragma unroll
        for (int t = 0; t < 16; ++t) {
            float m = rmin[tid * 16 + t];
            int   i = ridx[tid * 16 + t];
            if (m < best || (m == best && i < bi)) { best = m; bi = i; }
        }
        int row = row0 + tid;
        g_idx[row] = bi;
        atomicAdd(&g_hist[bi], 1);
        if (out_size >= QELEMS + 1 + NROWS)
            out[QELEMS + 1 + row] = (float)bi;   // indices output (as float)
    }
}

// ---------------------------------------------------------------------------
// Kernel 3: quantized = fl(f + fl(q - f)) — replicates the straight-through
// two-op fp32 sequence bitwise. One float4 per thread.
// ---------------------------------------------------------------------------
__global__ void vq_gather_kernel(const float* __restrict__ A,
                                 const float* __restrict__ cb,
                                 float* __restrict__ out) {
    long t   = (long)blockIdx.x * 256 + threadIdx.x;   // 0 .. 4194303
    int  row = (int)(t >> 6);
    int  j   = (int)(t & 63);
    int  idx = g_idx[row];
    float4 f = ((const float4*)A)[(long)row * 64 + j];
    float4 c = ((const float4*)cb)[(long)idx * 64 + j];
    float4 q;
    q.x = __fadd_rn(f.x, __fsub_rn(c.x, f.x));
    q.y = __fadd_rn(f.y, __fsub_rn(c.y, f.y));
    q.z = __fadd_rn(f.z, __fsub_rn(c.z, f.z));
    q.w = __fadd_rn(f.w, __fsub_rn(c.w, f.w));
    ((float4*)out)[(long)row * 64 + j] = q;
}

// ---------------------------------------------------------------------------
// Kernel 4: perplexity = exp(-sum p*log(p + 1e-10)), p = hist/N
// (scalar output; ulp-level log/exp differences are far below threshold)
// ---------------------------------------------------------------------------
__global__ void vq_perplexity_kernel(float* __restrict__ out) {
    __shared__ float s[1024];
    int t = threadIdx.x;
    float p = (float)g_hist[t] * (1.0f / (float)NROWS);
    s[t] = p * logf(p + 1e-10f);
    __syncthreads();
    for (int off = 512; off > 0; off >>= 1) {
        if (t < off) s[t] += s[t + off];
        __syncthreads();
    }
    if (t == 0) out[QELEMS] = expf(-s[0]);
}

// ---------------------------------------------------------------------------
extern "C" void kernel_launch(void* const* d_in, const int* in_sizes, int n_in,
                              void* d_out, int out_size) {
    const float* f_emb = (const float*)d_in[0];   // [65536, 256] flat
    const float* cb    = (const float*)d_in[1];   // [1024, 256]
    float* out = (float*)d_out;
    long osz = (long)out_size;

    vq_xnorm_kernel<<<NROWS / 256, 256>>>(f_emb);
    vq_prep_kernel<<<KCODES / 256, 256>>>(cb);
    vq_argmin_kernel<<<NROWS / BM, 256>>>(f_emb, cb, out, osz);
    vq_gather_kernel<<<(NROWS * 64) / 256, 256>>>(f_emb, cb, out);
    if (osz > QELEMS)
        vq_perplexity_kernel<<<1, 1024>>>(out);
}

// round 6
// speedup vs baseline: 1.1401x; 1.1401x over previous
#include <cuda_runtime.h>
#include <cuda_bf16.h>
#include <math.h>

// Problem constants
#define NROWS  65536      // 64*32*32
#define DDIM   256
#define KCODES 1024
#define QELEMS (65536L*256L)

// GEMM tiling
#define BM 128
#define BN 128
#define BKC 16
#define SPAD 4            // smem row padding (floats)

__device__ float g_enorm[KCODES];
__device__ float g_xnorm[NROWS];
__device__ int   g_hist[KCODES];
__device__ int   g_idx[NROWS];

// ---- packed f32x2 helpers (bit-identical: two independent fma.rn) ---------
__device__ __forceinline__ unsigned long long pk2(float lo, float hi) {
    unsigned long long r;
    asm("mov.b64 %0, {%1, %2};" : "=l"(r) : "f"(lo), "f"(hi));
    return r;
}
__device__ __forceinline__ void upk2(float& lo, float& hi, unsigned long long v) {
    asm("mov.b64 {%0, %1}, %2;" : "=f"(lo), "=f"(hi) : "l"(v));
}
__device__ __forceinline__ void fma2(unsigned long long& d,
                                     unsigned long long a,
                                     unsigned long long b) {
    asm("fma.rn.f32x2 %0, %1, %2, %0;" : "+l"(d) : "l"(a), "l"(b));
}

// ---------------------------------------------------------------------------
// Kernel 0: X[row] = sequential fp32 sum of fl(x*x), ascending order
// (bitwise order preserved). Coalesced via smem staging: block handles 256
// rows; 8 chunks of 32 columns each are loaded coalesced, then each thread
// accumulates its own row strictly in ascending column order.
// ---------------------------------------------------------------------------
__global__ void vq_xnorm_kernel(const float* __restrict__ A) {
    __shared__ float sc[256][33];     // pitch 33: conflict-free column reads
    int tid  = threadIdx.x;
    int row0 = blockIdx.x * 256;
    float s = 0.0f;
    for (int c = 0; c < 8; ++c) {
        __syncthreads();              // previous chunk fully consumed
        #pragma unroll
        for (int i = 0; i < 8; ++i) {
            int f = i * 256 + tid;    // 0..2047
            int r = f >> 3;           // row within block chunk
            int q = f & 7;            // float4 slot within 32 cols
            float4 v = *(const float4*)(A + (long)(row0 + r) * DDIM + c * 32 + q * 4);
            sc[r][q * 4 + 0] = v.x; sc[r][q * 4 + 1] = v.y;
            sc[r][q * 4 + 2] = v.z; sc[r][q * 4 + 3] = v.w;
        }
        __syncthreads();
        #pragma unroll
        for (int k = 0; k < 32; ++k) {
            float x = sc[tid][k];
            s = __fadd_rn(s, __fmul_rn(x, x));
        }
    }
    g_xnorm[row0 + tid] = s;
}

// ---------------------------------------------------------------------------
// Kernel 1: codebook row norms (sequential fp32, same discipline) + zero hist.
// ---------------------------------------------------------------------------
__global__ void vq_prep_kernel(const float* __restrict__ cb) {
    int w = blockIdx.x * 256 + threadIdx.x;    // 4 blocks x 256 = 1024
    if (w < KCODES) g_hist[w] = 0;
    const float4* p = (const float4*)(cb + (long)w * DDIM);
    float s = 0.0f;
    #pragma unroll 8
    for (int j = 0; j < DDIM / 4; ++j) {
        float4 v = p[j];
        s = __fadd_rn(s, __fmul_rn(v.x, v.x));
        s = __fadd_rn(s, __fmul_rn(v.y, v.y));
        s = __fadd_rn(s, __fmul_rn(v.z, v.z));
        s = __fadd_rn(s, __fmul_rn(v.w, v.w));
    }
    g_enorm[w] = s;
}

// ---------------------------------------------------------------------------
// Kernel 2: fused fp32 GEMM + argmin, packed-FFMA2 inner loop, double-buffered
// smem (1 sync per k-tile), register prefetch of the next tile.
// Each acc column keeps its exact ascending-k fp32 fma chain (FFMA2 halves
// are independent fma.rn) -> numerics identical to the passing R4 kernel.
// Distance = fl( fl(X + E) - fl(2*dot) ), explicit rn intrinsics.
// ---------------------------------------------------------------------------
__global__ void __launch_bounds__(256, 1)
vq_argmin_kernel(const float* __restrict__ A,     // f_emb flat [N, D]
                 const float* __restrict__ B,     // codebook   [K, D]
                 float* __restrict__ out,         // d_out (float)
                 long out_size) {
    __shared__ float As[2][BKC][BM + SPAD];
    __shared__ float Bs[2][BKC][BN + SPAD];

    const int tid = threadIdx.x;
    const int tx  = tid & 15;        // 0..15  column group
    const int ty  = tid >> 4;        // 0..15  row group
    const int row0 = blockIdx.x * BM;

    // per-thread loader indices (two float4 of A, two of B per tile)
    const int r0  = tid >> 2;                 // 0..63
    const int dc0 = (tid & 3) * 4;
    const int r1  = (tid + 256) >> 2;         // 64..127
    const int dc1 = dc0;                      // (tid+256)&3 == tid&3

    float runmin[8];
    int   runidx[8];
    float xv[8];
    #pragma unroll
    for (int i = 0; i < 8; ++i) {
        runmin[i] = INFINITY; runidx[i] = 0x7fffffff;
        int rl = (i < 4) ? (ty * 4 + i) : (64 + ty * 4 + (i - 4));
        xv[i] = g_xnorm[row0 + rl];
    }

    for (int nt = 0; nt < KCODES / BN; ++nt) {
        const int col0 = nt * BN;
        unsigned long long acc2[8][4];
        #pragma unroll
        for (int i = 0; i < 8; ++i)
            #pragma unroll
            for (int j = 0; j < 4; ++j) acc2[i][j] = 0ull;

        // prologue: tile kt=0 -> buf 0
        {
            float4 ra0 = *(const float4*)(A + (long)(row0 + r0) * DDIM + dc0);
            float4 ra1 = *(const float4*)(A + (long)(row0 + r1) * DDIM + dc1);
            float4 rb0 = *(const float4*)(B + (long)(col0 + r0) * DDIM + dc0);
            float4 rb1 = *(const float4*)(B + (long)(col0 + r1) * DDIM + dc1);
            As[0][dc0 + 0][r0] = ra0.x; As[0][dc0 + 1][r0] = ra0.y;
            As[0][dc0 + 2][r0] = ra0.z; As[0][dc0 + 3][r0] = ra0.w;
            As[0][dc1 + 0][r1] = ra1.x; As[0][dc1 + 1][r1] = ra1.y;
            As[0][dc1 + 2][r1] = ra1.z; As[0][dc1 + 3][r1] = ra1.w;
            Bs[0][dc0 + 0][r0] = rb0.x; Bs[0][dc0 + 1][r0] = rb0.y;
            Bs[0][dc0 + 2][r0] = rb0.z; Bs[0][dc0 + 3][r0] = rb0.w;
            Bs[0][dc1 + 0][r1] = rb1.x; Bs[0][dc1 + 1][r1] = rb1.y;
            Bs[0][dc1 + 2][r1] = rb1.z; Bs[0][dc1 + 3][r1] = rb1.w;
        }

        int p = 0;
        for (int kt = 0; kt < DDIM; kt += BKC) {
            __syncthreads();          // buf[p] ready; buf[p^1] free

            float4 ra0, ra1, rb0, rb1;
            const bool more = (kt + BKC) < DDIM;
            if (more) {               // prefetch next tile while computing
                int kn = kt + BKC;
                ra0 = *(const float4*)(A + (long)(row0 + r0) * DDIM + kn + dc0);
                ra1 = *(const float4*)(A + (long)(row0 + r1) * DDIM + kn + dc1);
                rb0 = *(const float4*)(B + (long)(col0 + r0) * DDIM + kn + dc0);
                rb1 = *(const float4*)(B + (long)(col0 + r1) * DDIM + kn + dc1);
            }

            #pragma unroll
            for (int dd = 0; dd < BKC; ++dd) {
                float4 t0 = *(const float4*)&As[p][dd][ty * 4];
                float4 t1 = *(const float4*)&As[p][dd][64 + ty * 4];
                float4 u0 = *(const float4*)&Bs[p][dd][tx * 4];
                float4 u1 = *(const float4*)&Bs[p][dd][64 + tx * 4];
                unsigned long long b2[4];
                b2[0] = pk2(u0.x, u0.y); b2[1] = pk2(u0.z, u0.w);
                b2[2] = pk2(u1.x, u1.y); b2[3] = pk2(u1.z, u1.w);
                float av[8] = {t0.x, t0.y, t0.z, t0.w, t1.x, t1.y, t1.z, t1.w};
                #pragma unroll
                for (int i = 0; i < 8; ++i) {
                    unsigned long long aa = pk2(av[i], av[i]);
                    fma2(acc2[i][0], aa, b2[0]);
                    fma2(acc2[i][1], aa, b2[1]);
                    fma2(acc2[i][2], aa, b2[2]);
                    fma2(acc2[i][3], aa, b2[3]);
                }
            }

            if (more) {               // store next tile into the other buffer
                int q = p ^ 1;
                As[q][dc0 + 0][r0] = ra0.x; As[q][dc0 + 1][r0] = ra0.y;
                As[q][dc0 + 2][r0] = ra0.z; As[q][dc0 + 3][r0] = ra0.w;
                As[q][dc1 + 0][r1] = ra1.x; As[q][dc1 + 1][r1] = ra1.y;
                As[q][dc1 + 2][r1] = ra1.z; As[q][dc1 + 3][r1] = ra1.w;
                Bs[q][dc0 + 0][r0] = rb0.x; Bs[q][dc0 + 1][r0] = rb0.y;
                Bs[q][dc0 + 2][r0] = rb0.z; Bs[q][dc0 + 3][r0] = rb0.w;
                Bs[q][dc1 + 0][r1] = rb1.x; Bs[q][dc1 + 1][r1] = rb1.y;
                Bs[q][dc1 + 2][r1] = rb1.z; Bs[q][dc1 + 3][r1] = rb1.w;
            }
            p ^= 1;
        }

        // Epilogue: d = fl(fl(X+E) - 2*dot), running first-min (lowest index).
        // Column pairs: b2[0]->(tx*4, tx*4+1), b2[1]->(tx*4+2, +3),
        //               b2[2]->(64+tx*4, +1), b2[3]->(64+tx*4+2, +3)
        #pragma unroll
        for (int jp = 0; jp < 4; ++jp) {
            int cb = col0 + ((jp < 2) ? (tx * 4 + jp * 2)
                                      : (64 + tx * 4 + (jp - 2) * 2));
            float en0 = g_enorm[cb];
            float en1 = g_enorm[cb + 1];
            #pragma unroll
            for (int ri = 0; ri < 8; ++ri) {
                float d0, d1;
                upk2(d0, d1, acc2[ri][jp]);
                float s0 = __fsub_rn(__fadd_rn(xv[ri], en0), __fmul_rn(2.0f, d0));
                float s1 = __fsub_rn(__fadd_rn(xv[ri], en1), __fmul_rn(2.0f, d1));
                if (s0 < runmin[ri]) { runmin[ri] = s0; runidx[ri] = cb; }
                if (s1 < runmin[ri]) { runmin[ri] = s1; runidx[ri] = cb + 1; }
            }
        }
        __syncthreads();   // all reads of smem bufs done before next prologue
    }

    // Cross-thread reduction: 16 column-threads per row, lowest index on tie.
    float* rmin = &As[0][0][0];
    int*   ridx = (int*)&Bs[0][0][0];
    #pragma unroll
    for (int ri = 0; ri < 8; ++ri) {
        int rl = (ri < 4) ? (ty * 4 + ri) : (64 + ty * 4 + (ri - 4));
        rmin[rl * 16 + tx] = runmin[ri];
        ridx[rl * 16 + tx] = runidx[ri];
    }
    __syncthreads();
    if (tid < BM) {
        float best = INFINITY; int bi = 0x7fffffff;
        #pragma unroll
        for (int t = 0; t < 16; ++t) {
            float m = rmin[tid * 16 + t];
            int   i = ridx[tid * 16 + t];
            if (m < best || (m == best && i < bi)) { best = m; bi = i; }
        }
        int row = row0 + tid;
        g_idx[row] = bi;
        atomicAdd(&g_hist[bi], 1);
        if (out_size >= QELEMS + 1 + NROWS)
            out[QELEMS + 1 + row] = (float)bi;   // indices output (as float)
    }
}

// ---------------------------------------------------------------------------
// Kernel 3: quantized = fl(f + fl(q - f)) — bitwise straight-through.
// ---------------------------------------------------------------------------
__global__ void vq_gather_kernel(const float* __restrict__ A,
                                 const float* __restrict__ cb,
                                 float* __restrict__ out) {
    long t   = (long)blockIdx.x * 256 + threadIdx.x;   // 0 .. 4194303
    int  row = (int)(t >> 6);
    int  j   = (int)(t & 63);
    int  idx = g_idx[row];
    float4 f = ((const float4*)A)[(long)row * 64 + j];
    float4 c = ((const float4*)cb)[(long)idx * 64 + j];
    float4 q;
    q.x = __fadd_rn(f.x, __fsub_rn(c.x, f.x));
    q.y = __fadd_rn(f.y, __fsub_rn(c.y, f.y));
    q.z = __fadd_rn(f.z, __fsub_rn(c.z, f.z));
    q.w = __fadd_rn(f.w, __fsub_rn(c.w, f.w));
    ((float4*)out)[(long)row * 64 + j] = q;
}

// ---------------------------------------------------------------------------
// Kernel 4: perplexity = exp(-sum p*log(p + 1e-10)), p = hist/N
// ---------------------------------------------------------------------------
__global__ void vq_perplexity_kernel(float* __restrict__ out) {
    __shared__ float s[1024];
    int t = threadIdx.x;
    float p = (float)g_hist[t] * (1.0f / (float)NROWS);
    s[t] = p * logf(p + 1e-10f);
    __syncthreads();
    for (int off = 512; off > 0; off >>= 1) {
        if (t < off) s[t] += s[t + off];
        __syncthreads();
    }
    if (t == 0) out[QELEMS] = expf(-s[0]);
}

// ---------------------------------------------------------------------------
extern "C" void kernel_launch(void* const* d_in, const int* in_sizes, int n_in,
                              void* d_out, int out_size) {
    const float* f_emb = (const float*)d_in[0];   // [65536, 256] flat
    const float* cb    = (const float*)d_in[1];   // [1024, 256]
    float* out = (float*)d_out;
    long osz = (long)out_size;

    vq_xnorm_kernel<<<NROWS / 256, 256>>>(f_emb);
    vq_prep_kernel<<<KCODES / 256, 256>>>(cb);
    vq_argmin_kernel<<<NROWS / BM, 256>>>(f_emb, cb, out, osz);
    vq_gather_kernel<<<(NROWS * 64) / 256, 256>>>(f_emb, cb, out);
    if (osz > QELEMS)
        vq_perplexity_kernel<<<1, 1024>>>(out);
}